// round 17
// baseline (speedup 1.0000x reference)
#include <cuda_runtime.h>
#include <cuda_fp16.h>
#include <math.h>
#include <stdint.h>

// ===========================================================================
// Fused INR via warp-level mma.sync, fp16 weights/acts, fp32 accum.
// R16 = R15 (persistent CTAs) +
//   * hybrid sin epilogue: 3/4 MUFU __sinf, 1/4 FMA-pipe poly (idle pipe)
//   * cross-layer A0 prefetch chain (next layer's first A frags loaded
//     under the sin wall, not after the barrier)
//   * per-layer bias hoist (LDG covered by k-loop)
// ===========================================================================

#define OMEGA0    30.0f
#define TWO_PI_F  6.283185307179586f
#define THREADS   256

#define NTILES    (512 + 5 * 1024)      // 5632 (mt,ks) tiles total
#define PLANE_U32 (NTILES * 128)        // u32 per plane (tile=128 u32)

__device__ __align__(16) uint32_t g_wfrag[PLANE_U32];   // fp16 weight fragments

// ---- SMEM layout (bytes) ----
#define SM_WOUT  0                       // 1536 floats
#define SM_CS    6144                    // 192 floats
#define SM_BFF   6912                    // 384 floats
#define SM_P0    9216                    // act plane 0: 512 rows x 128B
#define SM_P1    (SM_P0 + 65536)         // act plane 1
#define SMEM_BYTES (SM_P1 + 65536)       // 140288

// ---------------- helpers ----------------
__device__ __forceinline__ uint32_t smem_u32(const void* p) {
    uint32_t a;
    asm("{ .reg .u64 t; cvta.to.shared.u64 t, %1; cvt.u32.u64 %0, t; }"
        : "=r"(a) : "l"(p));
    return a;
}
__device__ __forceinline__ void mma16816(float* d, const uint4& a,
                                         uint32_t b0, uint32_t b1) {
    asm volatile(
        "mma.sync.aligned.m16n8k16.row.col.f32.f16.f16.f32 "
        "{%0,%1,%2,%3}, {%4,%5,%6,%7}, {%8,%9}, {%0,%1,%2,%3};"
        : "+f"(d[0]), "+f"(d[1]), "+f"(d[2]), "+f"(d[3])
        : "r"(a.x), "r"(a.y), "r"(a.z), "r"(a.w), "r"(b0), "r"(b1));
}
__device__ __forceinline__ void ldmx4t(uint32_t& r0, uint32_t& r1,
                                       uint32_t& r2, uint32_t& r3,
                                       uint32_t addr) {
    asm volatile(
        "ldmatrix.sync.aligned.m8n8.x4.trans.shared.b16 {%0,%1,%2,%3}, [%4];"
        : "=r"(r0), "=r"(r1), "=r"(r2), "=r"(r3) : "r"(addr));
}
__device__ __forceinline__ uint16_t hfb(float v) {
    __half h = __float2half_rn(v);
    return *reinterpret_cast<uint16_t*>(&h);
}
__device__ __forceinline__ float hff(uint16_t b) {
    __half h = *reinterpret_cast<__half*>(&b);
    return __half2float(h);
}

// FMA-pipe sine: 2-term pi reduction + deg-7 minimax. |x| <~ 60, abs err ~1e-6.
__device__ __forceinline__ float sin_poly(float x) {
    float q = rintf(x * 0.3183098861837907f);
    float r = fmaf(q, -3.140625f, x);
    r = fmaf(q, -9.676535897932e-4f, r);
    float r2 = r * r;
    float p = fmaf(r2, -1.9515296e-4f, 8.3321608e-3f);
    p = fmaf(r2, p, -1.6666654e-1f);
    p = fmaf(r * r2, p, r);
    int qi = (int)q;
    return __int_as_float(__float_as_int(p) ^ (qi << 31));
}

// store v (fp16) to (row, col n) in a plane, swizzled
__device__ __forceinline__ void store1(unsigned char* plane, int row, int n, float v) {
    uint32_t off = (uint32_t)row * 128u + (((uint32_t)n * 2u) ^ (((uint32_t)row & 7u) << 4));
    *(uint16_t*)(plane + off) = hfb(v);
}

// ---------------- weight prep: fp32 -> fragment-ordered fp16 ----------------
__global__ void prep_weights(const float* __restrict__ Wf,
                             const float* __restrict__ Wh) {
    int idx = blockIdx.x * blockDim.x + threadIdx.x;
    if (idx >= PLANE_U32) return;
    int tile = idx >> 7;
    int li   = idx & 127;
    int lane = li >> 2, q = li & 3;

    const float* src; int K, mt, ks;
    if (tile < 512) { mt = tile >> 4; ks = tile & 15; K = 256; src = Wf; }
    else {
        int th = tile - 512;
        int l = th >> 10, tt = th & 1023;
        mt = tt >> 5; ks = tt & 31; K = 512;
        src = Wh + (size_t)l * 512 * 512;
    }
    int r  = lane >> 2, c2 = (lane & 3) * 2;
    int row = mt * 16 + r + (q & 1) * 8;
    int k   = ks * 16 + c2 + (q >> 1) * 8;
    float w0 = src[(size_t)row * K + k];
    float w1 = src[(size_t)row * K + k + 1];
    g_wfrag[idx] = ((uint32_t)hfb(w1) << 16) | (uint32_t)hfb(w0);
}

// ---------------- one sine layer: src plane -> dst plane --------------------
// A[] holds this layer's ks=0 fragments on entry; on exit holds the NEXT
// layer's ks=0 fragments (loaded from whi_next with KSN k-steps).
template <int KS, int KSN>
__device__ __forceinline__ void run_layer(
    unsigned char* dst, uint32_t src_u32,
    const uint32_t* __restrict__ whi,
    const uint32_t* __restrict__ whi_next,
    const float* __restrict__ bias,
    int wid, int lane, uint4* A)
{
    const int r  = lane >> 2;
    const int cq = lane & 3;
    const int mid  = lane >> 3;
    const int rrow = lane & 7;
    const uint32_t rswz = (uint32_t)rrow << 4;
    const uint32_t krow_off = ((uint32_t)((mid & 1) * 8 + rrow)) * 128u;
    const uint32_t nb_base  = (uint32_t)((mid >> 1) * 8) * 2u;

    // bias hoist: LDG issued here, consumed only in epilogue (k-loop covers)
    float ob[4][2];
#pragma unroll
    for (int mtl = 0; mtl < 4; ++mtl) {
        int row0 = wid * 64 + mtl * 16 + r;
        ob[mtl][0] = OMEGA0 * __ldg(bias + row0);
        ob[mtl][1] = OMEGA0 * __ldg(bias + row0 + 8);
    }

    float acc[4][8][4];     // [m-tile][n-tile][frag]
#pragma unroll
    for (int a = 0; a < 4; ++a)
#pragma unroll
        for (int b = 0; b < 8; ++b)
#pragma unroll
            for (int c = 0; c < 4; ++c) acc[a][b][c] = 0.0f;

    const uint32_t* pA[4];
#pragma unroll
    for (int mt = 0; mt < 4; ++mt)
        pA[mt] = whi + (size_t)((wid * 4 + mt) * KS) * 128 + lane * 4;

    uint32_t baddr[4];
#pragma unroll
    for (int j = 0; j < 4; ++j)
        baddr[j] = src_u32 + krow_off + (((uint32_t)j * 32u + nb_base) ^ rswz);

    // prologue: B for ks=0 (A[] already preloaded by caller)
    uint4 nA[4];
    uint32_t B0[16], B1[16];
#pragma unroll
    for (int j = 0; j < 4; ++j)
        ldmx4t(B0[4 * j], B0[4 * j + 1], B0[4 * j + 2], B0[4 * j + 3],
               baddr[j]);

#pragma unroll 1
    for (int ks = 0; ks < KS; ks += 2) {
        // ---- even step: prefetch A(ks+1), B(ks+1); MMA on A,B0 ----
#pragma unroll
        for (int mt = 0; mt < 4; ++mt)
            nA[mt] = *(const uint4*)(pA[mt] + (ks + 1) * 128);
        {
            const uint32_t kb = (uint32_t)(ks + 1) * 2048u;
#pragma unroll
            for (int j = 0; j < 4; ++j)
                ldmx4t(B1[4 * j], B1[4 * j + 1], B1[4 * j + 2], B1[4 * j + 3],
                       baddr[j] + kb);
        }
#pragma unroll
        for (int nt = 0; nt < 8; ++nt)
#pragma unroll
            for (int mt = 0; mt < 4; ++mt)
                mma16816(acc[mt][nt], A[mt], B0[nt * 2], B0[nt * 2 + 1]);

        // ---- odd step: prefetch A(ks+2), B(ks+2); MMA on nA,B1 ----
        if (ks + 2 < KS) {
#pragma unroll
            for (int mt = 0; mt < 4; ++mt)
                A[mt] = *(const uint4*)(pA[mt] + (ks + 2) * 128);
            const uint32_t kb = (uint32_t)(ks + 2) * 2048u;
#pragma unroll
            for (int j = 0; j < 4; ++j)
                ldmx4t(B0[4 * j], B0[4 * j + 1], B0[4 * j + 2], B0[4 * j + 3],
                       baddr[j] + kb);
        }
#pragma unroll
        for (int nt = 0; nt < 8; ++nt)
#pragma unroll
            for (int mt = 0; mt < 4; ++mt)
                mma16816(acc[mt][nt], nA[mt], B1[nt * 2], B1[nt * 2 + 1]);
    }

    // ---- cross-layer A0 prefetch: next layer's ks=0 frags (L2 latency
    //      hides under the sin wall below; legal before the barrier) ----
#pragma unroll
    for (int mt = 0; mt < 4; ++mt)
        A[mt] = *(const uint4*)(whi_next +
                                (size_t)((wid * 4 + mt) * KSN) * 128 + lane * 4);

    // ---- epilogue: sin (3/4 MUFU, 1/4 FMA poly) -> f16x2 pack -> STS ----
#pragma unroll
    for (int mtl = 0; mtl < 4; ++mtl) {
        const int row0 = wid * 64 + mtl * 16 + r;
        const int row1 = row0 + 8;
        const float ob0 = ob[mtl][0];
        const float ob1 = ob[mtl][1];
        const uint32_t sw0 = ((uint32_t)row0 & 7u) << 4;
        const uint32_t sw1 = ((uint32_t)row1 & 7u) << 4;
#pragma unroll
        for (int nt = 0; nt < 8; ++nt) {
            const int n = nt * 8 + cq * 2;
            float v00, v01, v10, v11;
            if (mtl == 3) {   // FMA-pipe poly (overlaps other values' MUFU)
                v00 = sin_poly(fmaf(OMEGA0, acc[mtl][nt][0], ob0));
                v01 = sin_poly(fmaf(OMEGA0, acc[mtl][nt][1], ob0));
                v10 = sin_poly(fmaf(OMEGA0, acc[mtl][nt][2], ob1));
                v11 = sin_poly(fmaf(OMEGA0, acc[mtl][nt][3], ob1));
            } else {          // MUFU fast path
                v00 = __sinf(fmaf(OMEGA0, acc[mtl][nt][0], ob0));
                v01 = __sinf(fmaf(OMEGA0, acc[mtl][nt][1], ob0));
                v10 = __sinf(fmaf(OMEGA0, acc[mtl][nt][2], ob1));
                v11 = __sinf(fmaf(OMEGA0, acc[mtl][nt][3], ob1));
            }
            uint32_t hp0, hp1;
            asm("cvt.rn.f16x2.f32 %0, %1, %2;"
                : "=r"(hp0) : "f"(v01), "f"(v00));
            asm("cvt.rn.f16x2.f32 %0, %1, %2;"
                : "=r"(hp1) : "f"(v11), "f"(v10));
            uint32_t off0 = (uint32_t)row0 * 128u + (((uint32_t)n * 2u) ^ sw0);
            uint32_t off1 = (uint32_t)row1 * 128u + (((uint32_t)n * 2u) ^ sw1);
            *(uint32_t*)(dst + off0) = hp0;
            *(uint32_t*)(dst + off1) = hp1;
        }
    }
    __syncthreads();   // dst visible; src free for reuse as next dst
}

// ---------------- main kernel (persistent) ----------------
__global__ void __launch_bounds__(THREADS, 1)
inr_mma_kernel(const float* __restrict__ coords,
               const float* __restrict__ B_ff,
               const float* __restrict__ b_first,
               const float* __restrict__ b_hidden,
               const float* __restrict__ W_out,
               const float* __restrict__ b_out,
               float* __restrict__ out, int L)
{
    extern __shared__ unsigned char sm[];
    float* wout = (float*)(sm + SM_WOUT);
    float* cs   = (float*)(sm + SM_CS);
    float* bff  = (float*)(sm + SM_BFF);
    unsigned char* p0 = sm + SM_P0;
    unsigned char* p1 = sm + SM_P1;
    const uint32_t p0u = smem_u32(p0);
    const uint32_t p1u = smem_u32(p1);

    const int tid  = threadIdx.x;
    const int wid  = tid >> 5;
    const int lane = tid & 31;
    const int tiles = (L + 63) >> 6;

    // ---- one-time staging: B_ff, W_out, coords of first tile ----
    for (int i = tid; i < 384; i += THREADS) bff[i] = B_ff[i];
    for (int f = tid; f < 1536; f += THREADS) wout[f] = W_out[f];
    if ((int)blockIdx.x < tiles && tid < 192) {
        int g = blockIdx.x * 192 + tid;
        cs[tid] = (g < L * 3) ? coords[g] : 0.0f;
    }
    __syncthreads();

    // ---- preload layer-0 A0 fragments (tile-invariant) ----
    uint4 A[4];
#pragma unroll
    for (int mt = 0; mt < 4; ++mt)
        A[mt] = *(const uint4*)(g_wfrag +
                                (size_t)((wid * 4 + mt) * 16) * 128 + lane * 4);

#pragma unroll 1
    for (int t = blockIdx.x; t < tiles; t += gridDim.x) {
        const int pt0 = t * 64;

        // ---- Fourier features -> plane 0 (exact 2pi reduction) ----
        for (int e = tid; e < 8192; e += THREADS) {
            int j = e >> 6, m = e & 63;
            float tt = cs[m * 3 + 0] * bff[j] +
                       cs[m * 3 + 1] * bff[128 + j] +
                       cs[m * 3 + 2] * bff[256 + j];
            float f = tt - rintf(tt);
            float ang = TWO_PI_F * f;
            store1(p0, j, m, __sinf(ang));
            store1(p0, 128 + j, m, __cosf(ang));
        }
        __syncthreads();

        // ---- layers (A0 chained through each call) ----
        run_layer<16, 32>(p1, p0u, g_wfrag, g_wfrag + (size_t)512 * 128,
                          b_first, wid, lane, A);
#pragma unroll 1
        for (int l = 0; l < 4; ++l) {
            const size_t base  = (size_t)(512 + l * 1024) * 128;
            const size_t baseN = (size_t)(512 + (l + 1) * 1024) * 128;
            unsigned char* dst = (l & 1) ? p1 : p0;
            uint32_t src = (l & 1) ? p0u : p1u;
            run_layer<32, 32>(dst, src, g_wfrag + base, g_wfrag + baseN,
                              b_hidden + l * 512, wid, lane, A);
        }
        // last hidden layer: next-A = layer 0 of the NEXT tile (same data)
        run_layer<32, 16>(p0, p1u, g_wfrag + (size_t)(512 + 4 * 1024) * 128,
                          g_wfrag, b_hidden + 4 * 512, wid, lane, A);
        // final activations in P0

        // ---- prefetch next tile's coords (overlaps out-phase FMA) ----
        {
            int nt = t + gridDim.x;
            if (nt < tiles && tid < 192) {
                int g = nt * 192 + tid;
                cs[tid] = (g < L * 3) ? coords[g] : 0.0f;
            }
        }

        // ---- output linear 512 -> 3: 4 k-slices per point ----
        {
            const int p = tid >> 2;        // point 0..63
            const int s = tid & 3;         // k-slice 0..3
            float a0 = 0.0f, a1 = 0.0f, a2 = 0.0f;
#pragma unroll 4
            for (int kk = 0; kk < 128; ++kk) {
                const int k = s * 128 + kk;
                uint32_t off = (uint32_t)k * 128u +
                               (((uint32_t)p * 2u) ^ (((uint32_t)k & 7u) << 4));
                float hv = hff(*(uint16_t*)(p0 + off));
                a0 = fmaf(hv, wout[k], a0);
                a1 = fmaf(hv, wout[512 + k], a1);
                a2 = fmaf(hv, wout[1024 + k], a2);
            }
#pragma unroll
            for (int d = 2; d >= 1; d >>= 1) {
                a0 += __shfl_down_sync(0xFFFFFFFFu, a0, d, 4);
                a1 += __shfl_down_sync(0xFFFFFFFFu, a1, d, 4);
                a2 += __shfl_down_sync(0xFFFFFFFFu, a2, d, 4);
            }
            if (s == 0) {
                int gp = pt0 + p;
                if (gp < L) {
                    out[gp * 3 + 0] = a0 + __ldg(b_out + 0);
                    out[gp * 3 + 1] = a1 + __ldg(b_out + 1);
                    out[gp * 3 + 2] = a2 + __ldg(b_out + 2);
                }
            }
        }
        __syncthreads();   // out reads of P0 done; cs staged; next FF may run
    }
}

// ---------------- launcher ----------------
extern "C" void kernel_launch(void* const* d_in, const int* in_sizes, int n_in,
                              void* d_out, int out_size) {
    const float* coords   = (const float*)d_in[0];
    const float* B_ff     = (const float*)d_in[1];
    const float* W_first  = (const float*)d_in[2];
    const float* b_first  = (const float*)d_in[3];
    const float* W_hidden = (const float*)d_in[4];
    const float* b_hidden = (const float*)d_in[5];
    const float* W_out    = (const float*)d_in[6];
    const float* b_out    = (const float*)d_in[7];
    float* out = (float*)d_out;

    int L = in_sizes[0] / 3;
    int tiles = (L + 63) / 64;
    int blocks = tiles < 152 ? tiles : 152;   // GB300: 152 SMs, 1 CTA/SM

    prep_weights<<<(PLANE_U32 + 255) / 256, 256>>>(W_first, W_hidden);

    cudaFuncSetAttribute(inr_mma_kernel,
                         cudaFuncAttributeMaxDynamicSharedMemorySize,
                         SMEM_BYTES);
    inr_mma_kernel<<<blocks, THREADS, SMEM_BYTES>>>(
        coords, B_ff, b_first, b_hidden, W_out, b_out, out, L);
}